// round 3
// baseline (speedup 1.0000x reference)
#include <cuda_runtime.h>

#define SEQ   1024
#define BATCH 512
#define NC    48
#define FULL  0xffffffffu
#define PD    8          // global prefetch depth (steps)

// ---- packed f32x2 helpers (sm_103a) ------------------------------------
static __device__ __forceinline__ unsigned long long pk2(float lo, float hi) {
    unsigned long long r;
    asm("mov.b64 %0, {%1,%2};" : "=l"(r) : "f"(lo), "f"(hi));
    return r;
}
static __device__ __forceinline__ unsigned long long fma2(
    unsigned long long a, unsigned long long b, unsigned long long c) {
    unsigned long long d;
    asm("fma.rn.f32x2 %0, %1, %2, %3;" : "=l"(d) : "l"(a), "l"(b), "l"(c));
    return d;
}
static __device__ __forceinline__ unsigned long long add2(
    unsigned long long a, unsigned long long b) {
    unsigned long long d;
    asm("add.rn.f32x2 %0, %1, %2;" : "=l"(d) : "l"(a), "l"(b));
    return d;
}
static __device__ __forceinline__ float hadd2(unsigned long long v) {
    float lo, hi;
    asm("mov.b64 {%0,%1}, %2;" : "=f"(lo), "=f"(hi) : "l"(v));
    return lo + hi;
}
static __device__ __forceinline__ float lo2(unsigned long long v) {
    float lo, hi;
    asm("mov.b64 {%0,%1}, %2;" : "=f"(lo), "=f"(hi) : "l"(v));
    return lo;
}
static __device__ __forceinline__ void lds16(
    unsigned long long& x, unsigned long long& y, unsigned int addr) {
    asm volatile("ld.shared.v2.u64 {%0,%1}, [%2];" : "=l"(x), "=l"(y) : "r"(addr));
}
static __device__ __forceinline__ float frcp(float x) {
    float r; asm("rcp.approx.f32 %0, %1;" : "=f"(r) : "f"(x)); return r;
}

// ---------------------------------------------------------------------------
// Fused kernel. Block = 256 threads, 4 batches per block:
//   warps 0-3: forward algorithm (logZ) for batch 4*blk+wid  (one per SMSP)
//   warps 4-7: target-path score X, handed over via shared flag.
//
// logZ: exp-domain recurrence u_t = diag(w_t) * E^T * u_{t-1},
// E = exp(transitions) in registers as row-paired f32x2.
// One-step-delayed renormalization by alpha_prev[0] (read for free from the
// first LDS.128 of the exchange buffer); Mlog += log(r) compensates exactly.
// Score rows prefetched PD=8 steps ahead in a register ring (hides ~577cyc
// DRAM latency, which R2 profiling showed was the binding chain).
// ---------------------------------------------------------------------------
__global__ __launch_bounds__(256, 1) void crf_fused_kernel(
    const float* __restrict__ scores,
    const int*   __restrict__ target,
    const int*   __restrict__ lengths,
    const float* __restrict__ trans,
    float*       __restrict__ out)
{
    __shared__ float sh_a[4][2][64];   // [warp][pingpong][48 used + pad]
    __shared__ float sh_X[4];
    __shared__ int   sh_flag[4];

    const int wid  = threadIdx.x >> 5;
    const int lane = threadIdx.x & 31;

    if (wid < 4 && lane == 0) sh_flag[wid] = 0;
    __syncthreads();

    if (wid >= 4) {
        // ---------------- X role (overlapped with logZ loop) ----------------
        const int w = wid - 4;
        const int b = blockIdx.x * 4 + w;
        const int L = lengths[b];
        float part = 0.0f;
        for (int t = lane; t < L; t += 32) {
            const int tgt = target[t * BATCH + b];
            float v = scores[((size_t)t * BATCH + b) * NC + tgt];
            if (t > 0) v += trans[target[(t - 1) * BATCH + b] * NC + tgt];
            part += v;
        }
#pragma unroll
        for (int o = 16; o > 0; o >>= 1)
            part += __shfl_xor_sync(FULL, part, o);
        if (lane == 0) {
            sh_X[w] = part;
            __threadfence_block();
            atomicExch(&sh_flag[w], 1);
        }
        return;
    }

    // ------------------------- logZ role -----------------------------------
    const int  b  = blockIdx.x * 4 + wid;
    const int  c0 = lane;
    const bool v1 = (lane < 16);
    const int  c1 = v1 ? (lane + 32) : lane;   // safe dup index; masked below

    // exp(transitions) as row-paired f32x2, one column pair per lane.
    unsigned long long eTp0[24], eTp1[24];
#pragma unroll
    for (int k = 0; k < 24; ++k) {
        float x0 = __expf(trans[(2 * k)     * NC + c0]);
        float y0 = __expf(trans[(2 * k + 1) * NC + c0]);
        eTp0[k] = pk2(x0, y0);
        float x1 = v1 ? __expf(trans[(2 * k)     * NC + c1]) : 0.0f;
        float y1 = v1 ? __expf(trans[(2 * k + 1) * NC + c1]) : 0.0f;
        eTp1[k] = pk2(x1, y1);
    }

    const int L = lengths[b];
    const float* sp0 = scores + (size_t)b * NC + c0;
    const float* sp1 = scores + (size_t)b * NC + c1;
    const size_t rowstride = (size_t)BATCH * NC;

    float a0   = __expf(sp0[0]);
    float a1   = v1 ? __expf(sp1[0]) : 0.0f;
    float Mlog = 0.0f;

    // PD-deep register ring prefetch of score rows (clamped, always in-bounds).
    float p0[PD], p1[PD];
#pragma unroll
    for (int k = 0; k < PD; ++k) {
        int tt = 1 + k; if (tt > SEQ - 1) tt = SEQ - 1;
        p0[k] = sp0[(size_t)tt * rowstride];
        p1[k] = v1 ? sp1[(size_t)tt * rowstride] : 0.0f;
    }

    unsigned int shbase[2];
    shbase[0] = (unsigned int)__cvta_generic_to_shared(&sh_a[wid][0][0]);
    shbase[1] = (unsigned int)__cvta_generic_to_shared(&sh_a[wid][1][0]);

    for (int t = 1; t < L; ++t) {
        const int slot  = (t - 1) & 1;
        const int pslot = (t - 1) & (PD - 1);

        const float s0 = p0[pslot];
        const float s1 = p1[pslot];
        {   // prefetch t+PD (clamped) into the ring slot just consumed
            int tn = t + PD; if (tn > SEQ - 1) tn = SEQ - 1;
            p0[pslot] = sp0[(size_t)tn * rowstride];
            p1[pslot] = v1 ? sp1[(size_t)tn * rowstride] : 0.0f;
        }
        const float w0 = __expf(s0);
        const float w1 = __expf(s1);

        // exchange alpha through shared (ping-pong -> single syncwarp)
        {
            float* shp = &sh_a[wid][slot][0];
            shp[lane]      = a0;
            shp[32 + lane] = a1;
        }
        __syncwarp();

        const unsigned int sb = shbase[slot];

        // 8 independent FMA2 chains, each 6 deep.
        unsigned long long cA0 = 0ull, cA1 = 0ull, cA2 = 0ull, cA3 = 0ull;
        unsigned long long cB0 = 0ull, cB1 = 0ull, cB2 = 0ull, cB3 = 0ull;
        unsigned long long e01_first = 0ull;
#pragma unroll
        for (int k = 0; k < 12; k += 2) {
            unsigned long long x01, x23, y01, y23;
            lds16(x01, x23, sb + 16u * k);
            lds16(y01, y23, sb + 16u * (k + 1));
            if (k == 0) e01_first = x01;
            cA0 = fma2(x01, eTp0[2 * k],     cA0);
            cA1 = fma2(x23, eTp0[2 * k + 1], cA1);
            cB0 = fma2(x01, eTp1[2 * k],     cB0);
            cB1 = fma2(x23, eTp1[2 * k + 1], cB1);
            cA2 = fma2(y01, eTp0[2 * k + 2], cA2);
            cA3 = fma2(y23, eTp0[2 * k + 3], cA3);
            cB2 = fma2(y01, eTp1[2 * k + 2], cB2);
            cB3 = fma2(y23, eTp1[2 * k + 3], cB3);
        }

        // delayed-norm reference = alpha_prev[0] = low word of first LDS
        const float r   = lo2(e01_first);
        const float inv = frcp(r);
        Mlog += __logf(r);
        const float m0 = w0 * inv;
        const float m1 = w1 * inv;

        const float dot0 = hadd2(add2(add2(cA0, cA1), add2(cA2, cA3)));
        const float dot1 = hadd2(add2(add2(cB0, cB1), add2(cB2, cB3)));

        a0 = dot0 * m0;
        a1 = dot1 * m1;   // stays 0 for lanes >= 16 (eTp1 == 0 there)
    }

    // logZ = Mlog + log(sum_j a[j])
    float ssum = a0 + (v1 ? a1 : 0.0f);
#pragma unroll
    for (int o = 16; o > 0; o >>= 1)
        ssum += __shfl_xor_sync(FULL, ssum, o);

    if (lane == 0) {
        const float logZ = Mlog + __logf(ssum);
        // X warp of the same block finishes in ~13us << our loop: no real wait.
        while (atomicAdd(&sh_flag[wid], 0) == 0) { }
        __threadfence_block();
        const float X = sh_X[wid];
        out[b]         = X;
        out[BATCH + b] = X - logZ;
    }
}

// ---------------------------------------------------------------------------
extern "C" void kernel_launch(void* const* d_in, const int* in_sizes, int n_in,
                              void* d_out, int out_size)
{
    const float* scores  = (const float*)d_in[0];  // (1024, 512, 48) f32
    const int*   target  = (const int*)  d_in[1];  // (1024, 512) i32
    const int*   lengths = (const int*)  d_in[2];  // (512,) i32
    const float* trans   = (const float*)d_in[3];  // (48, 48) f32
    float* out = (float*)d_out;                    // (2, 512) f32

    crf_fused_kernel<<<BATCH / 4, 256>>>(scores, target, lengths, trans, out);
}